// round 15
// baseline (speedup 1.0000x reference)
#include <cuda_runtime.h>
#include <cuda_fp16.h>
#include <math.h>
#include <stdint.h>

#define BB 32
#define LL 2048
#define PP 512
#define KK 64
#define NT (BB*LL)   // 65536 tokens
#define VOCAB 50257

// ---- scratch (device globals: no allocation allowed) ----
__device__ float g_t[NT];                                // max-over-k pre-softmax
__device__ float g_beta[NT];                             // softmax weights (incl. 1/L)
__device__ __align__(16) __half g_VCh[(size_t)VOCAB*KK]; // norm(V) @ Chat^T, fp16
__device__ __align__(16) __half g_VWh[(size_t)VOCAB*KK]; // V @ f2w^T, fp16
// fragments pre-baked into m16n8k16 B layout (fp16):
// [c16 (32)][ntile (8)][lane (32)] -> uint2 {b0, b1}
__device__ __align__(16) uint2 g_Bfrag[32*8*32];         // normalized centroids
__device__ __align__(16) uint2 g_Wfrag[32*8*32];         // f2_w

// ============================================================
// helpers
// ============================================================
__device__ __forceinline__ void mma16816(float* d, const uint32_t* a, const uint32_t* b) {
    asm volatile(
        "mma.sync.aligned.m16n8k16.row.col.f32.f16.f16.f32 "
        "{%0,%1,%2,%3}, {%4,%5,%6,%7}, {%8,%9}, {%0,%1,%2,%3};"
        : "+f"(d[0]), "+f"(d[1]), "+f"(d[2]), "+f"(d[3])
        : "r"(a[0]), "r"(a[1]), "r"(a[2]), "r"(a[3]), "r"(b[0]), "r"(b[1]));
}
#define LDSM4(r, addr) \
    asm volatile("ldmatrix.sync.aligned.m8n8.x4.shared.b16 {%0,%1,%2,%3}, [%4];" \
        : "=r"((r)[0]), "=r"((r)[1]), "=r"((r)[2]), "=r"((r)[3]) : "r"(addr))

__device__ __forceinline__ uint32_t packh2(float a, float b) {
    __half2 h = __floats2half2_rn(a, b);
    return *(uint32_t*)&h;
}

// ============================================================
// K0a: bake f2_w fragments
// ============================================================
__global__ void k_fragW(const float* __restrict__ W) {
    int idx = blockIdx.x * 256 + threadIdx.x;   // 8192
    int l   = idx & 31;
    int nt  = (idx >> 5) & 7;
    int c16 = idx >> 8;
    int n = nt*8 + (l >> 2);
    int k = c16*16 + (l & 3)*2;
    g_Wfrag[idx] = make_uint2(
        packh2(W[n*PP + k],     W[n*PP + k + 1]),
        packh2(W[n*PP + k + 8], W[n*PP + k + 9]));
}

// ============================================================
// K0b: centroid norms + B fragments. CTA n (64).
// ============================================================
__global__ __launch_bounds__(256) void k_setupC(const float* __restrict__ C) {
    int n = blockIdx.x;
    int tid = threadIdx.x;
    __shared__ float ws[8];
    __shared__ float s_inv;

    float s = 0.f;
    for (int p = tid; p < PP; p += 256) { float v = C[n*PP + p]; s += v*v; }
    for (int o = 16; o; o >>= 1) s += __shfl_xor_sync(0xffffffffu, s, o);
    if ((tid & 31) == 0) ws[tid >> 5] = s;
    __syncthreads();
    if (tid == 0)
        s_inv = rsqrtf(ws[0]+ws[1]+ws[2]+ws[3]+ws[4]+ws[5]+ws[6]+ws[7]);
    __syncthreads();
    float inv = s_inv;

    int nt = n >> 3;
    int lbase = (n & 7) * 4;
    for (int item = tid; item < 128; item += 256) {
        int c16 = item >> 2, j = item & 3;
        int k = c16*16 + j*2;
        int fidx = c16*256 + nt*32 + lbase + j;
        g_Bfrag[fidx] = make_uint2(
            packh2(C[n*PP + k]     * inv, C[n*PP + k + 1] * inv),
            packh2(C[n*PP + k + 8] * inv, C[n*PP + k + 9] * inv));
    }
}

// ============================================================
// K0c: out bias init (keeps k_vocab in ncu slot #4)
// ============================================================
__global__ void k_outbias(const float* __restrict__ f2b, float* __restrict__ out) {
    int t = blockIdx.x * 512 + threadIdx.x;
    out[t] = f2b[t & 63];
}

// ============================================================
// K1: vocab GEMM pair. 786 CTAs = 393 row-tiles x 2, 128 rows/CTA.
// K=512 in 4 chunks of 128 (one sync per chunk, 64 MMAs/warp per chunk).
// Even CTA: VCh (+norm fold). Odd: VWh.
// dyn smem: Ah 2 x (128 rows x 272 B) = 69632, sqs @69632 -> 70144 B
// ============================================================
#define ASTR2 136       // fp16 row stride in halves (272 B)
#define ABUF 34816      // one buffer, bytes
#define SMV_TOT 70144

__global__ __launch_bounds__(256, 2) void k_vocab(const float* __restrict__ V) {
    extern __shared__ char sm[];
    __half* Ah = (__half*)sm;
    float* sqs = (float*)(sm + 2*ABUF);

    int tid = threadIdx.x;
    int w   = tid >> 5;
    int l   = tid & 31;
    int isW = blockIdx.x & 1;
    int t0  = (blockIdx.x >> 1) * 128;

    int seg  = l & 15;
    int rsub = l >> 4;

    float acc[8][4];
    #pragma unroll
    for (int nt = 0; nt < 8; nt++)
        #pragma unroll
        for (int i = 0; i < 4; i++) acc[nt][i] = 0.f;
    float sq[8];
    #pragma unroll
    for (int j = 0; j < 8; j++) sq[j] = 0.f;

    uint32_t smA0 = (uint32_t)__cvta_generic_to_shared(Ah);
    int arow_lm = w*16 + (l & 7) + ((l >> 3) & 1) * 8;
    uint32_t a_off = (uint32_t)(arow_lm*272 + (l >> 4)*16);
    const uint2* fbase = isW ? g_Wfrag : g_Bfrag;

    // row base pointers (clamped)
    const float* rp[8];
    #pragma unroll
    for (int j = 0; j < 8; j++) {
        int v = t0 + w*16 + j*2 + rsub;
        if (v >= VOCAB) v = VOCAB - 1;
        rp[j] = V + (size_t)v*PP + seg*4;
    }

    // prefetch chunk 0 first half
    float4 R[8];
    #pragma unroll
    for (int j = 0; j < 8; j++) R[j] = *(const float4*)(rp[j]);

    for (int c = 0; c < 4; c++) {
        int buf = c & 1;
        __half* A = (__half*)(sm + buf*ABUF);
        // issue second-half loads first (fly under convert of R)
        float4 R2[8];
        #pragma unroll
        for (int j = 0; j < 8; j++)
            R2[j] = *(const float4*)(rp[j] + c*128 + 64);
        // convert first half (cols 0-63 of this chunk)
        #pragma unroll
        for (int j = 0; j < 8; j++) {
            float4 v = R[j];
            sq[j] = fmaf(v.x, v.x, fmaf(v.y, v.y, fmaf(v.z, v.z, fmaf(v.w, v.w, sq[j]))));
            int row = w*16 + j*2 + rsub;
            *(uint2*)&A[row*ASTR2 + seg*4] =
                make_uint2(packh2(v.x, v.y), packh2(v.z, v.w));
        }
        // convert second half (cols 64-127)
        #pragma unroll
        for (int j = 0; j < 8; j++) {
            float4 v = R2[j];
            sq[j] = fmaf(v.x, v.x, fmaf(v.y, v.y, fmaf(v.z, v.z, fmaf(v.w, v.w, sq[j]))));
            int row = w*16 + j*2 + rsub;
            *(uint2*)&A[row*ASTR2 + 64 + seg*4] =
                make_uint2(packh2(v.x, v.y), packh2(v.z, v.w));
        }
        // prefetch next chunk's first half (hidden under MMA phase)
        if (c < 3) {
            #pragma unroll
            for (int j = 0; j < 8; j++)
                R[j] = *(const float4*)(rp[j] + (c+1)*128);
        }
        __syncthreads();
        // consume: 8 k16 sub-chunks
        uint32_t smA = smA0 + (uint32_t)buf * (uint32_t)ABUF;
        #pragma unroll
        for (int kc = 0; kc < 8; kc++) {
            uint32_t a[4];
            LDSM4(a, smA + a_off + kc*32);
            int c16 = c*8 + kc;
            const uint2* bp = fbase + (size_t)c16*256 + l;
            #pragma unroll
            for (int nt = 0; nt < 8; nt++) {
                uint2 b = __ldg(bp + nt*32);
                mma16816(acc[nt], a, (const uint32_t*)&b);
            }
        }
        __syncthreads();   // all warps done with buf before overwrite (2 bufs -> next use is c+2; safe with single sync thanks to double buffer? keep for safety on buf reuse)
    }

    // norms (even CTAs): reduce per-row squares
    float inv0 = 1.f, inv1 = 1.f;
    int arow = w*16 + (l >> 2);
    if (!isW) {
        #pragma unroll
        for (int j = 0; j < 8; j++) {
            float s = sq[j];
            s += __shfl_xor_sync(0xffffffffu, s, 1);
            s += __shfl_xor_sync(0xffffffffu, s, 2);
            s += __shfl_xor_sync(0xffffffffu, s, 4);
            s += __shfl_xor_sync(0xffffffffu, s, 8);
            if (seg == 0) sqs[w*16 + j*2 + rsub] = s;
        }
        __syncwarp();
        inv0 = rsqrtf(sqs[arow]);
        inv1 = rsqrtf(sqs[arow + 8]);
    }

    __half* dst = isW ? g_VWh : g_VCh;
    int v0 = t0 + arow;
    int v1 = v0 + 8;
    int col0 = (l & 3)*2;
    #pragma unroll
    for (int nt = 0; nt < 8; nt++) {
        if (v0 < VOCAB)
            *(uint32_t*)&dst[(size_t)v0*KK + nt*8 + col0] =
                packh2(acc[nt][0]*inv0, acc[nt][1]*inv0);
        if (v1 < VOCAB)
            *(uint32_t*)&dst[(size_t)v1*KK + nt*8 + col0] =
                packh2(acc[nt][2]*inv1, acc[nt][3]*inv1);
    }
}

// ============================================================
// K2: fused expand + 11-tap conv + bias + relu + max over K -> g_t[b,l]
// ============================================================
__global__ __launch_bounds__(256) void k_conv(const int* __restrict__ x,
                                              const float* __restrict__ f1_w,
                                              const float* __restrict__ f1_b) {
    __shared__ float Gs[138*66];
    __shared__ float wsm[11];
    __shared__ float bias[64];
    int b  = blockIdx.y;
    int l0 = blockIdx.x * 128;
    int tid = threadIdx.x;
    if (tid < 11) wsm[tid] = f1_w[tid];
    if (tid < 64) bias[tid] = f1_b[tid];

    for (int idx = tid; idx < 138*16; idx += 256) {
        int row = idx >> 4, q = idx & 15;
        int l = l0 - 5 + row;
        float4 v = make_float4(0.f, 0.f, 0.f, 0.f);
        if ((unsigned)l < (unsigned)LL) {
            int tok = __ldg(&x[b*LL + l]);
            uint2 hv = *(const uint2*)&g_VCh[(size_t)tok*KK + q*4];
            float2 lo = __half22float2(*(__half2*)&hv.x);
            float2 hi = __half22float2(*(__half2*)&hv.y);
            v = make_float4(lo.x, lo.y, hi.x, hi.y);
        }
        int k0 = q*4;
        float vv[4] = {v.x, v.y, v.z, v.w};
        #pragma unroll
        for (int i = 0; i < 4; i++) {
            int k = k0 + i;
            Gs[row*66 + 2*(k & 31) + (k >> 5)] = vv[i];
        }
    }
    __syncthreads();

    float wreg[11];
    #pragma unroll
    for (int j = 0; j < 11; j++) wreg[j] = wsm[j];

    int lane = tid & 31;
    int kg = lane & 15;
    int lg = (tid >> 5)*2 + (lane >> 4);
    int L0 = lg * 8;

    float tmax[8];
    #pragma unroll
    for (int i = 0; i < 8; i++) tmax[i] = 0.f;

    #pragma unroll
    for (int kk = 0; kk < 4; kk++) {
        int k = kg + 16*kk;
        int cp = 2*(k & 31) + (k >> 5);
        float bk = bias[k];
        float win[18];
        #pragma unroll
        for (int m = 0; m < 18; m++) win[m] = Gs[(L0 + m)*66 + cp];
        #pragma unroll
        for (int i = 0; i < 8; i++) {
            float u = 0.f;
            #pragma unroll
            for (int j = 0; j < 11; j++) u = fmaf(wreg[j], win[i + j], u);
            tmax[i] = fmaxf(tmax[i], fmaxf(u + bk, 0.f));
        }
    }
    #pragma unroll
    for (int i = 0; i < 8; i++) {
        float t = tmax[i];
        t = fmaxf(t, __shfl_xor_sync(0xffffffffu, t, 1));
        t = fmaxf(t, __shfl_xor_sync(0xffffffffu, t, 2));
        t = fmaxf(t, __shfl_xor_sync(0xffffffffu, t, 4));
        t = fmaxf(t, __shfl_xor_sync(0xffffffffu, t, 8));
        if (kg == 0) g_t[(size_t)b*LL + l0 + L0 + i] = t;
    }
}

// ============================================================
// K3: single-pass softmax over L (folds 1/L)
// ============================================================
__global__ __launch_bounds__(512) void k_softmax() {
    int b = blockIdx.x;
    int tid = threadIdx.x;
    int wid = tid >> 5, lid = tid & 31;
    __shared__ float red[16], red2[16];

    float4 v = ((const float4*)(g_t + (size_t)b*LL))[tid];

    float mx = fmaxf(fmaxf(v.x, v.y), fmaxf(v.z, v.w));
    for (int o = 16; o; o >>= 1) mx = fmaxf(mx, __shfl_xor_sync(0xffffffffu, mx, o));
    if (lid == 0) red[wid] = mx;
    __syncthreads();
    if (wid == 0) {
        float m = red[lid & 15];
        for (int o = 8; o; o >>= 1) m = fmaxf(m, __shfl_xor_sync(0xffffffffu, m, o));
        if (lid == 0) red[0] = m;
    }
    __syncthreads();
    float m = red[0];

    float e0 = expf(v.x - m), e1 = expf(v.y - m), e2 = expf(v.z - m), e3 = expf(v.w - m);
    float s = e0 + e1 + e2 + e3;
    for (int o = 16; o; o >>= 1) s += __shfl_xor_sync(0xffffffffu, s, o);
    if (lid == 0) red2[wid] = s;
    __syncthreads();
    if (wid == 0) {
        float t = red2[lid & 15];
        for (int o = 8; o; o >>= 1) t += __shfl_xor_sync(0xffffffffu, t, o);
        if (lid == 0) red2[0] = t;
    }
    __syncthreads();
    float scale = 1.f / (red2[0] * (float)LL);

    ((float4*)(g_beta + (size_t)b*LL))[tid] =
        make_float4(e0*scale, e1*scale, e2*scale, e3*scale);
}

// ============================================================
// K4: out[b,k] += sum_l beta[b,l] * VWh[x[b,l], k]   (fp16 table)
// ============================================================
__global__ __launch_bounds__(128) void k_poolvw(const int* __restrict__ x,
                                                float* __restrict__ out) {
    __shared__ float4 red[128];
    int blk = blockIdx.x;
    int b = blk >> 4, c = blk & 15;
    int t = threadIdx.x;
    int i = t >> 4;
    int q = t & 15;
    int lbase = b*LL + c*128;

    float4 acc = make_float4(0.f, 0.f, 0.f, 0.f);
    #pragma unroll 4
    for (int it = 0; it < 16; it++) {
        int l = it*8 + i;
        float wgt = g_beta[lbase + l];
        int row = __ldg(&x[lbase + l]);
        uint2 hv = *(const uint2*)&g_VWh[(size_t)row*KK + q*4];
        float2 lo = __half22float2(*(__half2*)&hv.x);
        float2 hi = __half22float2(*(__half2*)&hv.y);
        acc.x = fmaf(wgt, lo.x, acc.x);
        acc.y = fmaf(wgt, lo.y, acc.y);
        acc.z = fmaf(wgt, hi.x, acc.z);
        acc.w = fmaf(wgt, hi.y, acc.w);
    }
    red[t] = acc;
    __syncthreads();
    if (t < 64) {
        float4 o = red[t + 64];
        acc = red[t];
        acc.x += o.x; acc.y += o.y; acc.z += o.z; acc.w += o.w;
        red[t] = acc;
    }
    __syncthreads();
    if (t < 32) {
        float4 o = red[t + 32];
        acc = red[t];
        acc.x += o.x; acc.y += o.y; acc.z += o.z; acc.w += o.w;
        red[t] = acc;
    }
    __syncthreads();
    if (t < 16) {
        float4 o = red[t + 16];
        acc = red[t];
        acc.x += o.x; acc.y += o.y; acc.z += o.z; acc.w += o.w;
        atomicAdd(&out[b*KK + t*4 + 0], acc.x);
        atomicAdd(&out[b*KK + t*4 + 1], acc.y);
        atomicAdd(&out[b*KK + t*4 + 2], acc.z);
        atomicAdd(&out[b*KK + t*4 + 3], acc.w);
    }
}

// ============================================================
extern "C" void kernel_launch(void* const* d_in, const int* in_sizes, int n_in,
                              void* d_out, int out_size) {
    const int*   x   = (const int*)d_in[0];
    const float* V   = (const float*)d_in[1];
    const float* C   = (const float*)d_in[2];
    const float* f1w = (const float*)d_in[3];
    const float* f1b = (const float*)d_in[4];
    const float* f2w = (const float*)d_in[5];
    const float* f2b = (const float*)d_in[6];
    float* out = (float*)d_out;

    cudaFuncSetAttribute(k_vocab, cudaFuncAttributeMaxDynamicSharedMemorySize, SMV_TOT);

    k_fragW<<<32, 256>>>(f2w);                          // 1
    k_setupC<<<KK, 256>>>(C);                           // 2
    k_outbias<<<4, 512>>>(f2b, out);                    // 3
    k_vocab<<<((VOCAB + 127)/128)*2, 256, SMV_TOT>>>(V);// 4 <- ncu slot
    k_conv<<<dim3(LL/128, BB), 256>>>(x, f1w, f1b);     // 5
    k_softmax<<<BB, 512>>>();                           // 6
    k_poolvw<<<BB*16, 128>>>(x, out);                   // 7
}

// round 16
// speedup vs baseline: 2.4058x; 2.4058x over previous
#include <cuda_runtime.h>
#include <cuda_fp16.h>
#include <math.h>
#include <stdint.h>

#define BB 32
#define LL 2048
#define PP 512
#define KK 64
#define NT (BB*LL)   // 65536 tokens
#define VOCAB 50257

// ---- scratch (device globals: no allocation allowed) ----
__device__ float g_t[NT];                                // max-over-k pre-softmax
__device__ float g_beta[NT];                             // softmax weights (incl. 1/L)
__device__ __align__(16) __half g_VCh[(size_t)VOCAB*KK]; // norm(V) @ Chat^T, fp16
__device__ __align__(16) __half g_VWh[(size_t)VOCAB*KK]; // V @ f2w^T, fp16
// fragments pre-baked into m16n8k16 B layout (fp16):
// [c16 (32)][ntile (8)][lane (32)] -> uint2 {b0, b1}
__device__ __align__(16) uint2 g_Bfrag[32*8*32];         // normalized centroids
__device__ __align__(16) uint2 g_Wfrag[32*8*32];         // f2_w

// ============================================================
// helpers
// ============================================================
__device__ __forceinline__ void mma16816(float* d, const uint32_t* a, const uint32_t* b) {
    asm volatile(
        "mma.sync.aligned.m16n8k16.row.col.f32.f16.f16.f32 "
        "{%0,%1,%2,%3}, {%4,%5,%6,%7}, {%8,%9}, {%0,%1,%2,%3};"
        : "+f"(d[0]), "+f"(d[1]), "+f"(d[2]), "+f"(d[3])
        : "r"(a[0]), "r"(a[1]), "r"(a[2]), "r"(a[3]), "r"(b[0]), "r"(b[1]));
}
#define LDSM4(r, addr) \
    asm volatile("ldmatrix.sync.aligned.m8n8.x4.shared.b16 {%0,%1,%2,%3}, [%4];" \
        : "=r"((r)[0]), "=r"((r)[1]), "=r"((r)[2]), "=r"((r)[3]) : "r"(addr))

__device__ __forceinline__ uint32_t packh2(float a, float b) {
    __half2 h = __floats2half2_rn(a, b);
    return *(uint32_t*)&h;
}
__device__ __forceinline__ void cp16(uint32_t dst, const void* src) {
    asm volatile("cp.async.cg.shared.global [%0], [%1], 16;" :: "r"(dst), "l"(src));
}
#define CP_COMMIT()  asm volatile("cp.async.commit_group;")
#define CP_WAIT1()   asm volatile("cp.async.wait_group 1;")
#define CP_WAIT0()   asm volatile("cp.async.wait_group 0;")

// ============================================================
// K0a: bake f2_w fragments
// ============================================================
__global__ void k_fragW(const float* __restrict__ W) {
    int idx = blockIdx.x * 256 + threadIdx.x;   // 8192
    int l   = idx & 31;
    int nt  = (idx >> 5) & 7;
    int c16 = idx >> 8;
    int n = nt*8 + (l >> 2);
    int k = c16*16 + (l & 3)*2;
    g_Wfrag[idx] = make_uint2(
        packh2(W[n*PP + k],     W[n*PP + k + 1]),
        packh2(W[n*PP + k + 8], W[n*PP + k + 9]));
}

// ============================================================
// K0b: centroid norms + B fragments. CTA n (64).
// ============================================================
__global__ __launch_bounds__(256) void k_setupC(const float* __restrict__ C) {
    int n = blockIdx.x;
    int tid = threadIdx.x;
    __shared__ float ws[8];
    __shared__ float s_inv;

    float s = 0.f;
    for (int p = tid; p < PP; p += 256) { float v = C[n*PP + p]; s += v*v; }
    for (int o = 16; o; o >>= 1) s += __shfl_xor_sync(0xffffffffu, s, o);
    if ((tid & 31) == 0) ws[tid >> 5] = s;
    __syncthreads();
    if (tid == 0)
        s_inv = rsqrtf(ws[0]+ws[1]+ws[2]+ws[3]+ws[4]+ws[5]+ws[6]+ws[7]);
    __syncthreads();
    float inv = s_inv;

    int nt = n >> 3;
    int lbase = (n & 7) * 4;
    for (int item = tid; item < 128; item += 256) {
        int c16 = item >> 2, j = item & 3;
        int k = c16*16 + j*2;
        int fidx = c16*256 + nt*32 + lbase + j;
        g_Bfrag[fidx] = make_uint2(
            packh2(C[n*PP + k]     * inv, C[n*PP + k + 1] * inv),
            packh2(C[n*PP + k + 8] * inv, C[n*PP + k + 9] * inv));
    }
}

// ============================================================
// K0c: out bias init (keeps k_vocab in the profiled slot)
// ============================================================
__global__ void k_outbias(const float* __restrict__ f2b, float* __restrict__ out) {
    int t = blockIdx.x * 512 + threadIdx.x;
    out[t] = f2b[t & 63];
}

// ============================================================
// K1: vocab GEMM pair, cp.async depth-2 gather pipeline.
// 786 CTAs = 393 row-tiles x 2, 128 rows/CTA, K=512 in 8 chunks of 64.
// Even CTA: VCh (+norm fold). Odd CTA: VWh.
// smem: staging fp32 2x32768 @0, Ah fp16 2x18432 @65536, sqs @102400
// ============================================================
#define ASTRH 72        // fp16 row stride (144B)
#define STG_BUF 32768
#define AH_OFF 65536
#define AH_BUF 18432
#define SQS_OFF 102400
#define SMV_TOT 102912

__global__ __launch_bounds__(256, 2) void k_vocab(const float* __restrict__ V) {
    extern __shared__ char sm[];
    float* sqs = (float*)(sm + SQS_OFF);

    int tid = threadIdx.x;
    int w   = tid >> 5;
    int l   = tid & 31;
    int isW = blockIdx.x & 1;
    int t0  = (blockIdx.x >> 1) * 128;

    int seg  = l & 15;
    int rsub = l >> 4;

    float acc[8][4];
    #pragma unroll
    for (int nt = 0; nt < 8; nt++)
        #pragma unroll
        for (int i = 0; i < 4; i++) acc[nt][i] = 0.f;
    float sq[8];
    #pragma unroll
    for (int j = 0; j < 8; j++) sq[j] = 0.f;

    uint32_t smBase = (uint32_t)__cvta_generic_to_shared(sm);
    int arow_lm = w*16 + (l & 7) + ((l >> 3) & 1) * 8;
    uint32_t a_off = (uint32_t)(arow_lm*144 + (l >> 4)*16);
    const uint2* fbase = isW ? g_Wfrag : g_Bfrag;

    // per-thread row pointers (clamped) and staging byte offsets
    const float* rp[8];
    #pragma unroll
    for (int j = 0; j < 8; j++) {
        int v = t0 + w*16 + j*2 + rsub;
        if (v >= VOCAB) v = VOCAB - 1;
        rp[j] = V + (size_t)v*PP + seg*4;
    }
    int rowBase = w*16 + rsub;                 // + j*2
    uint32_t stgOff0 = (uint32_t)(rowBase*256 + seg*16);

    // prologue: stage chunks 0 and 1
    #pragma unroll
    for (int j = 0; j < 8; j++)
        cp16(smBase + stgOff0 + (uint32_t)(j*512), rp[j]);
    CP_COMMIT();
    #pragma unroll
    for (int j = 0; j < 8; j++)
        cp16(smBase + STG_BUF + stgOff0 + (uint32_t)(j*512), rp[j] + 64);
    CP_COMMIT();

    for (int c = 0; c < 8; c++) {
        int buf = c & 1;
        if (c < 7) { CP_WAIT1(); } else { CP_WAIT0(); }
        // convert own staged rows -> fp16 A (thread-private staging region)
        float* stg = (float*)(sm + buf*STG_BUF);
        __half* A  = (__half*)(sm + AH_OFF + buf*AH_BUF);
        #pragma unroll
        for (int j = 0; j < 8; j++) {
            int row = rowBase + j*2;
            float4 v = *(float4*)&stg[row*64 + seg*4];
            sq[j] = fmaf(v.x, v.x, fmaf(v.y, v.y, fmaf(v.z, v.z, fmaf(v.w, v.w, sq[j]))));
            *(uint2*)&A[row*ASTRH + seg*4] =
                make_uint2(packh2(v.x, v.y), packh2(v.z, v.w));
        }
        // stage chunk c+2 into this buffer (own region already consumed)
        if (c < 6) {
            #pragma unroll
            for (int j = 0; j < 8; j++)
                cp16(smBase + (uint32_t)buf*STG_BUF + stgOff0 + (uint32_t)(j*512),
                     rp[j] + (c+2)*64);
            CP_COMMIT();
        }
        __syncthreads();
        // consume: 4 k16 sub-chunks (proven R12 MMA phase)
        uint32_t smA = smBase + AH_OFF + (uint32_t)buf*AH_BUF;
        #pragma unroll
        for (int kc = 0; kc < 4; kc++) {
            uint32_t a[4];
            LDSM4(a, smA + a_off + kc*32);
            int c16 = c*4 + kc;
            const uint2* bp = fbase + (size_t)c16*256 + l;
            #pragma unroll
            for (int nt = 0; nt < 8; nt++) {
                uint2 b = __ldg(bp + nt*32);
                mma16816(acc[nt], a, (const uint32_t*)&b);
            }
        }
    }

    // norms (even CTAs): reduce per-row squares over 16 seg lanes
    float inv0 = 1.f, inv1 = 1.f;
    int arow = w*16 + (l >> 2);
    if (!isW) {
        #pragma unroll
        for (int j = 0; j < 8; j++) {
            float s = sq[j];
            s += __shfl_xor_sync(0xffffffffu, s, 1);
            s += __shfl_xor_sync(0xffffffffu, s, 2);
            s += __shfl_xor_sync(0xffffffffu, s, 4);
            s += __shfl_xor_sync(0xffffffffu, s, 8);
            if (seg == 0) sqs[w*16 + j*2 + rsub] = s;
        }
        __syncwarp();
        inv0 = rsqrtf(sqs[arow]);
        inv1 = rsqrtf(sqs[arow + 8]);
    }

    __half* dst = isW ? g_VWh : g_VCh;
    int v0 = t0 + arow;
    int v1 = v0 + 8;
    int col0 = (l & 3)*2;
    #pragma unroll
    for (int nt = 0; nt < 8; nt++) {
        if (v0 < VOCAB)
            *(uint32_t*)&dst[(size_t)v0*KK + nt*8 + col0] =
                packh2(acc[nt][0]*inv0, acc[nt][1]*inv0);
        if (v1 < VOCAB)
            *(uint32_t*)&dst[(size_t)v1*KK + nt*8 + col0] =
                packh2(acc[nt][2]*inv1, acc[nt][3]*inv1);
    }
}

// ============================================================
// K2: fused expand + 11-tap conv + bias + relu + max over K -> g_t[b,l]
// ============================================================
__global__ __launch_bounds__(256) void k_conv(const int* __restrict__ x,
                                              const float* __restrict__ f1_w,
                                              const float* __restrict__ f1_b) {
    __shared__ float Gs[138*66];
    __shared__ float wsm[11];
    __shared__ float bias[64];
    int b  = blockIdx.y;
    int l0 = blockIdx.x * 128;
    int tid = threadIdx.x;
    if (tid < 11) wsm[tid] = f1_w[tid];
    if (tid < 64) bias[tid] = f1_b[tid];

    for (int idx = tid; idx < 138*16; idx += 256) {
        int row = idx >> 4, q = idx & 15;
        int l = l0 - 5 + row;
        float4 v = make_float4(0.f, 0.f, 0.f, 0.f);
        if ((unsigned)l < (unsigned)LL) {
            int tok = __ldg(&x[b*LL + l]);
            uint2 hv = *(const uint2*)&g_VCh[(size_t)tok*KK + q*4];
            float2 lo = __half22float2(*(__half2*)&hv.x);
            float2 hi = __half22float2(*(__half2*)&hv.y);
            v = make_float4(lo.x, lo.y, hi.x, hi.y);
        }
        int k0 = q*4;
        float vv[4] = {v.x, v.y, v.z, v.w};
        #pragma unroll
        for (int i = 0; i < 4; i++) {
            int k = k0 + i;
            Gs[row*66 + 2*(k & 31) + (k >> 5)] = vv[i];
        }
    }
    __syncthreads();

    float wreg[11];
    #pragma unroll
    for (int j = 0; j < 11; j++) wreg[j] = wsm[j];

    int lane = tid & 31;
    int kg = lane & 15;
    int lg = (tid >> 5)*2 + (lane >> 4);
    int L0 = lg * 8;

    float tmax[8];
    #pragma unroll
    for (int i = 0; i < 8; i++) tmax[i] = 0.f;

    #pragma unroll
    for (int kk = 0; kk < 4; kk++) {
        int k = kg + 16*kk;
        int cp = 2*(k & 31) + (k >> 5);
        float bk = bias[k];
        float win[18];
        #pragma unroll
        for (int m = 0; m < 18; m++) win[m] = Gs[(L0 + m)*66 + cp];
        #pragma unroll
        for (int i = 0; i < 8; i++) {
            float u = 0.f;
            #pragma unroll
            for (int j = 0; j < 11; j++) u = fmaf(wreg[j], win[i + j], u);
            tmax[i] = fmaxf(tmax[i], fmaxf(u + bk, 0.f));
        }
    }
    #pragma unroll
    for (int i = 0; i < 8; i++) {
        float t = tmax[i];
        t = fmaxf(t, __shfl_xor_sync(0xffffffffu, t, 1));
        t = fmaxf(t, __shfl_xor_sync(0xffffffffu, t, 2));
        t = fmaxf(t, __shfl_xor_sync(0xffffffffu, t, 4));
        t = fmaxf(t, __shfl_xor_sync(0xffffffffu, t, 8));
        if (kg == 0) g_t[(size_t)b*LL + l0 + L0 + i] = t;
    }
}

// ============================================================
// K3: single-pass softmax over L (folds 1/L)
// ============================================================
__global__ __launch_bounds__(512) void k_softmax() {
    int b = blockIdx.x;
    int tid = threadIdx.x;
    int wid = tid >> 5, lid = tid & 31;
    __shared__ float red[16], red2[16];

    float4 v = ((const float4*)(g_t + (size_t)b*LL))[tid];

    float mx = fmaxf(fmaxf(v.x, v.y), fmaxf(v.z, v.w));
    for (int o = 16; o; o >>= 1) mx = fmaxf(mx, __shfl_xor_sync(0xffffffffu, mx, o));
    if (lid == 0) red[wid] = mx;
    __syncthreads();
    if (wid == 0) {
        float m = red[lid & 15];
        for (int o = 8; o; o >>= 1) m = fmaxf(m, __shfl_xor_sync(0xffffffffu, m, o));
        if (lid == 0) red[0] = m;
    }
    __syncthreads();
    float m = red[0];

    float e0 = expf(v.x - m), e1 = expf(v.y - m), e2 = expf(v.z - m), e3 = expf(v.w - m);
    float s = e0 + e1 + e2 + e3;
    for (int o = 16; o; o >>= 1) s += __shfl_xor_sync(0xffffffffu, s, o);
    if (lid == 0) red2[wid] = s;
    __syncthreads();
    if (wid == 0) {
        float t = red2[lid & 15];
        for (int o = 8; o; o >>= 1) t += __shfl_xor_sync(0xffffffffu, t, o);
        if (lid == 0) red2[0] = t;
    }
    __syncthreads();
    float scale = 1.f / (red2[0] * (float)LL);

    ((float4*)(g_beta + (size_t)b*LL))[tid] =
        make_float4(e0*scale, e1*scale, e2*scale, e3*scale);
}

// ============================================================
// K4: out[b,k] += sum_l beta[b,l] * VWh[x[b,l], k]   (fp16 table)
// ============================================================
__global__ __launch_bounds__(128) void k_poolvw(const int* __restrict__ x,
                                                float* __restrict__ out) {
    __shared__ float4 red[128];
    int blk = blockIdx.x;
    int b = blk >> 4, c = blk & 15;
    int t = threadIdx.x;
    int i = t >> 4;
    int q = t & 15;
    int lbase = b*LL + c*128;

    float4 acc = make_float4(0.f, 0.f, 0.f, 0.f);
    #pragma unroll 4
    for (int it = 0; it < 16; it++) {
        int l = it*8 + i;
        float wgt = g_beta[lbase + l];
        int row = __ldg(&x[lbase + l]);
        uint2 hv = *(const uint2*)&g_VWh[(size_t)row*KK + q*4];
        float2 lo = __half22float2(*(__half2*)&hv.x);
        float2 hi = __half22float2(*(__half2*)&hv.y);
        acc.x = fmaf(wgt, lo.x, acc.x);
        acc.y = fmaf(wgt, lo.y, acc.y);
        acc.z = fmaf(wgt, hi.x, acc.z);
        acc.w = fmaf(wgt, hi.y, acc.w);
    }
    red[t] = acc;
    __syncthreads();
    if (t < 64) {
        float4 o = red[t + 64];
        acc = red[t];
        acc.x += o.x; acc.y += o.y; acc.z += o.z; acc.w += o.w;
        red[t] = acc;
    }
    __syncthreads();
    if (t < 32) {
        float4 o = red[t + 32];
        acc = red[t];
        acc.x += o.x; acc.y += o.y; acc.z += o.z; acc.w += o.w;
        red[t] = acc;
    }
    __syncthreads();
    if (t < 16) {
        float4 o = red[t + 16];
        acc = red[t];
        acc.x += o.x; acc.y += o.y; acc.z += o.z; acc.w += o.w;
        atomicAdd(&out[b*KK + t*4 + 0], acc.x);
        atomicAdd(&out[b*KK + t*4 + 1], acc.y);
        atomicAdd(&out[b*KK + t*4 + 2], acc.z);
        atomicAdd(&out[b*KK + t*4 + 3], acc.w);
    }
}

// ============================================================
extern "C" void kernel_launch(void* const* d_in, const int* in_sizes, int n_in,
                              void* d_out, int out_size) {
    const int*   x   = (const int*)d_in[0];
    const float* V   = (const float*)d_in[1];
    const float* C   = (const float*)d_in[2];
    const float* f1w = (const float*)d_in[3];
    const float* f1b = (const float*)d_in[4];
    const float* f2w = (const float*)d_in[5];
    const float* f2b = (const float*)d_in[6];
    float* out = (float*)d_out;

    cudaFuncSetAttribute(k_vocab, cudaFuncAttributeMaxDynamicSharedMemorySize, SMV_TOT);

    k_fragW<<<32, 256>>>(f2w);                          // 1
    k_setupC<<<KK, 256>>>(C);                           // 2
    k_outbias<<<4, 512>>>(f2b, out);                    // 3
    k_vocab<<<((VOCAB + 127)/128)*2, 256, SMV_TOT>>>(V);// 4 <- ncu slot
    k_conv<<<dim3(LL/128, BB), 256>>>(x, f1w, f1b);     // 5
    k_softmax<<<BB, 512>>>();                           // 6
    k_poolvw<<<BB*16, 128>>>(x, out);                   // 7
}

// round 17
// speedup vs baseline: 2.9170x; 1.2125x over previous
#include <cuda_runtime.h>
#include <cuda_fp16.h>
#include <math.h>
#include <stdint.h>

#define BB 32
#define LL 2048
#define PP 512
#define KK 64
#define NT (BB*LL)   // 65536 tokens
#define VOCAB 50257

// ---- scratch (device globals: no allocation allowed) ----
__device__ float g_t[NT];                                // max-over-k pre-softmax
__device__ float g_beta[NT];                             // softmax weights (incl. 1/L)
__device__ __align__(16) __half g_VCh[(size_t)VOCAB*KK]; // norm(V) @ Chat^T, fp16
__device__ __align__(16) __half g_VWh[(size_t)VOCAB*KK]; // V @ f2w^T, fp16
__device__ __align__(16) uint2 g_Bfrag[32*8*32];         // centroid fragments
__device__ __align__(16) uint2 g_Wfrag[32*8*32];         // f2_w fragments
__device__ int g_cnt;                                    // # unique tokens
__device__ int g_list[VOCAB + 128];                      // unique token rows
__device__ unsigned char g_used[VOCAB];                  // per-replay flags

// ============================================================
// helpers
// ============================================================
__device__ __forceinline__ void mma16816(float* d, const uint32_t* a, const uint32_t* b) {
    asm volatile(
        "mma.sync.aligned.m16n8k16.row.col.f32.f16.f16.f32 "
        "{%0,%1,%2,%3}, {%4,%5,%6,%7}, {%8,%9}, {%0,%1,%2,%3};"
        : "+f"(d[0]), "+f"(d[1]), "+f"(d[2]), "+f"(d[3])
        : "r"(a[0]), "r"(a[1]), "r"(a[2]), "r"(a[3]), "r"(b[0]), "r"(b[1]));
}
#define LDSM4(r, addr) \
    asm volatile("ldmatrix.sync.aligned.m8n8.x4.shared.b16 {%0,%1,%2,%3}, [%4];" \
        : "=r"((r)[0]), "=r"((r)[1]), "=r"((r)[2]), "=r"((r)[3]) : "r"(addr))

__device__ __forceinline__ uint32_t packh2(float a, float b) {
    __half2 h = __floats2half2_rn(a, b);
    return *(uint32_t*)&h;
}
__device__ __forceinline__ void cp16(uint32_t dst, const void* src) {
    asm volatile("cp.async.cg.shared.global [%0], [%1], 16;" :: "r"(dst), "l"(src));
}
#define CP_COMMIT()  asm volatile("cp.async.commit_group;")
#define CP_WAIT1()   asm volatile("cp.async.wait_group 1;")
#define CP_WAIT0()   asm volatile("cp.async.wait_group 0;")

// ============================================================
// K0: setup. CTA n (64): centroid-n norm, B+W fragments; zero flags/cnt.
// ============================================================
__global__ __launch_bounds__(256) void k_setup(const float* __restrict__ C,
                                               const float* __restrict__ W) {
    int n = blockIdx.x;
    int tid = threadIdx.x;
    __shared__ float ws[8];
    __shared__ float s_inv;

    // zero used flags + counter (64 CTAs x 256 = 16384 strided)
    for (int i = n*256 + tid; i < VOCAB; i += 64*256) g_used[i] = 0;
    if (n == 0 && tid == 0) g_cnt = 0;

    float s = 0.f;
    for (int p = tid; p < PP; p += 256) { float v = C[n*PP + p]; s += v*v; }
    for (int o = 16; o; o >>= 1) s += __shfl_xor_sync(0xffffffffu, s, o);
    if ((tid & 31) == 0) ws[tid >> 5] = s;
    __syncthreads();
    if (tid == 0)
        s_inv = rsqrtf(ws[0]+ws[1]+ws[2]+ws[3]+ws[4]+ws[5]+ws[6]+ws[7]);
    __syncthreads();
    float inv = s_inv;

    int nt = n >> 3;
    int lbase = (n & 7) * 4;
    for (int item = tid; item < 128; item += 256) {
        int c16 = item >> 2, j = item & 3;
        int k = c16*16 + j*2;
        int fidx = c16*256 + nt*32 + lbase + j;
        g_Bfrag[fidx] = make_uint2(
            packh2(C[n*PP + k]     * inv, C[n*PP + k + 1] * inv),
            packh2(C[n*PP + k + 8] * inv, C[n*PP + k + 9] * inv));
        g_Wfrag[fidx] = make_uint2(
            packh2(W[n*PP + k],     W[n*PP + k + 1]),
            packh2(W[n*PP + k + 8], W[n*PP + k + 9]));
    }
}

// ============================================================
// K0b: flag used tokens + init out with bias. 128 CTAs x 512.
// ============================================================
__global__ void k_flag(const int* __restrict__ x,
                       const float* __restrict__ f2b,
                       float* __restrict__ out) {
    int i = blockIdx.x*512 + threadIdx.x;
    g_used[x[i]] = 1;
    if (i < BB*KK) out[i] = f2b[i & 63];
}

// ============================================================
// K0c: compact flagged rows into g_list (warp-aggregated).
// ============================================================
__global__ void k_compact() {
    int i = blockIdx.x*256 + threadIdx.x;
    int lane = threadIdx.x & 31;
    bool f = (i < VOCAB) && g_used[i];
    unsigned m = __ballot_sync(0xffffffffu, f);
    int c = __popc(m);
    int base = 0;
    if (lane == 0 && c) base = atomicAdd(&g_cnt, c);
    base = __shfl_sync(0xffffffffu, base, 0);
    if (f) g_list[base + __popc(m & ((1u << lane) - 1u))] = i;
}

// ============================================================
// K1: vocab GEMM pair over COMPACTED rows. cp.async depth-2 pipeline.
// grid 786 (worst case; CTAs past cnt exit). 128 rows/CTA, 8 chunks of 64.
// Even CTA: VCh (+norm fold). Odd CTA: VWh.
// smem: staging fp32 2x32768 @0, Ah fp16 2x18432 @65536, sqs @102400,
//       rows @102912 -> 103424 total
// ============================================================
#define ASTRH 72
#define STG_BUF 32768
#define AH_OFF 65536
#define AH_BUF 18432
#define SQS_OFF 102400
#define ROWS_OFF 102912
#define SMV_TOT 103424

__global__ __launch_bounds__(256, 2) void k_vocab(const float* __restrict__ V) {
    extern __shared__ char sm[];
    float* sqs  = (float*)(sm + SQS_OFF);
    int*   rows = (int*)(sm + ROWS_OFF);

    int tid = threadIdx.x;
    int w   = tid >> 5;
    int l   = tid & 31;
    int isW = blockIdx.x & 1;
    int t0  = (blockIdx.x >> 1) * 128;

    int cnt = g_cnt;
    if (t0 >= cnt) return;

    if (tid < 128) {
        int idx = t0 + tid;
        if (idx >= cnt) idx = cnt - 1;   // duplicate tail row (identical writes)
        rows[tid] = g_list[idx];
    }
    __syncthreads();

    int seg  = l & 15;
    int rsub = l >> 4;

    float acc[8][4];
    #pragma unroll
    for (int nt = 0; nt < 8; nt++)
        #pragma unroll
        for (int i = 0; i < 4; i++) acc[nt][i] = 0.f;
    float sq[8];
    #pragma unroll
    for (int j = 0; j < 8; j++) sq[j] = 0.f;

    uint32_t smBase = (uint32_t)__cvta_generic_to_shared(sm);
    int arow_lm = w*16 + (l & 7) + ((l >> 3) & 1) * 8;
    uint32_t a_off = (uint32_t)(arow_lm*144 + (l >> 4)*16);
    const uint2* fbase = isW ? g_Wfrag : g_Bfrag;

    const float* rp[8];
    #pragma unroll
    for (int j = 0; j < 8; j++)
        rp[j] = V + (size_t)rows[w*16 + j*2 + rsub]*PP + seg*4;
    int rowBase = w*16 + rsub;
    uint32_t stgOff0 = (uint32_t)(rowBase*256 + seg*16);

    // prologue: stage chunks 0 and 1
    #pragma unroll
    for (int j = 0; j < 8; j++)
        cp16(smBase + stgOff0 + (uint32_t)(j*512), rp[j]);
    CP_COMMIT();
    #pragma unroll
    for (int j = 0; j < 8; j++)
        cp16(smBase + STG_BUF + stgOff0 + (uint32_t)(j*512), rp[j] + 64);
    CP_COMMIT();

    for (int c = 0; c < 8; c++) {
        int buf = c & 1;
        if (c < 7) { CP_WAIT1(); } else { CP_WAIT0(); }
        float* stg = (float*)(sm + buf*STG_BUF);
        __half* A  = (__half*)(sm + AH_OFF + buf*AH_BUF);
        #pragma unroll
        for (int j = 0; j < 8; j++) {
            int row = rowBase + j*2;
            float4 v = *(float4*)&stg[row*64 + seg*4];
            sq[j] = fmaf(v.x, v.x, fmaf(v.y, v.y, fmaf(v.z, v.z, fmaf(v.w, v.w, sq[j]))));
            *(uint2*)&A[row*ASTRH + seg*4] =
                make_uint2(packh2(v.x, v.y), packh2(v.z, v.w));
        }
        if (c < 6) {
            #pragma unroll
            for (int j = 0; j < 8; j++)
                cp16(smBase + (uint32_t)buf*STG_BUF + stgOff0 + (uint32_t)(j*512),
                     rp[j] + (c+2)*64);
            CP_COMMIT();
        }
        __syncthreads();
        uint32_t smA = smBase + AH_OFF + (uint32_t)buf*AH_BUF;
        #pragma unroll
        for (int kc = 0; kc < 4; kc++) {
            uint32_t a[4];
            LDSM4(a, smA + a_off + kc*32);
            int c16 = c*4 + kc;
            const uint2* bp = fbase + (size_t)c16*256 + l;
            #pragma unroll
            for (int nt = 0; nt < 8; nt++) {
                uint2 b = __ldg(bp + nt*32);
                mma16816(acc[nt], a, (const uint32_t*)&b);
            }
        }
    }

    float inv0 = 1.f, inv1 = 1.f;
    int arow = w*16 + (l >> 2);
    if (!isW) {
        #pragma unroll
        for (int j = 0; j < 8; j++) {
            float s = sq[j];
            s += __shfl_xor_sync(0xffffffffu, s, 1);
            s += __shfl_xor_sync(0xffffffffu, s, 2);
            s += __shfl_xor_sync(0xffffffffu, s, 4);
            s += __shfl_xor_sync(0xffffffffu, s, 8);
            if (seg == 0) sqs[w*16 + j*2 + rsub] = s;
        }
        __syncwarp();
        inv0 = rsqrtf(sqs[arow]);
        inv1 = rsqrtf(sqs[arow + 8]);
    }

    __half* dst = isW ? g_VWh : g_VCh;
    int v0 = rows[arow];
    int v1 = rows[arow + 8];
    int col0 = (l & 3)*2;
    #pragma unroll
    for (int nt = 0; nt < 8; nt++) {
        *(uint32_t*)&dst[(size_t)v0*KK + nt*8 + col0] =
            packh2(acc[nt][0]*inv0, acc[nt][1]*inv0);
        *(uint32_t*)&dst[(size_t)v1*KK + nt*8 + col0] =
            packh2(acc[nt][2]*inv1, acc[nt][3]*inv1);
    }
}

// ============================================================
// K2: fused expand + 11-tap conv + bias + relu + max over K -> g_t[b,l]
// ============================================================
__global__ __launch_bounds__(256) void k_conv(const int* __restrict__ x,
                                              const float* __restrict__ f1_w,
                                              const float* __restrict__ f1_b) {
    __shared__ float Gs[138*66];
    __shared__ float wsm[11];
    __shared__ float bias[64];
    int b  = blockIdx.y;
    int l0 = blockIdx.x * 128;
    int tid = threadIdx.x;
    if (tid < 11) wsm[tid] = f1_w[tid];
    if (tid < 64) bias[tid] = f1_b[tid];

    for (int idx = tid; idx < 138*16; idx += 256) {
        int row = idx >> 4, q = idx & 15;
        int l = l0 - 5 + row;
        float4 v = make_float4(0.f, 0.f, 0.f, 0.f);
        if ((unsigned)l < (unsigned)LL) {
            int tok = __ldg(&x[b*LL + l]);
            uint2 hv = *(const uint2*)&g_VCh[(size_t)tok*KK + q*4];
            float2 lo = __half22float2(*(__half2*)&hv.x);
            float2 hi = __half22float2(*(__half2*)&hv.y);
            v = make_float4(lo.x, lo.y, hi.x, hi.y);
        }
        int k0 = q*4;
        float vv[4] = {v.x, v.y, v.z, v.w};
        #pragma unroll
        for (int i = 0; i < 4; i++) {
            int k = k0 + i;
            Gs[row*66 + 2*(k & 31) + (k >> 5)] = vv[i];
        }
    }
    __syncthreads();

    float wreg[11];
    #pragma unroll
    for (int j = 0; j < 11; j++) wreg[j] = wsm[j];

    int lane = tid & 31;
    int kg = lane & 15;
    int lg = (tid >> 5)*2 + (lane >> 4);
    int L0 = lg * 8;

    float tmax[8];
    #pragma unroll
    for (int i = 0; i < 8; i++) tmax[i] = 0.f;

    #pragma unroll
    for (int kk = 0; kk < 4; kk++) {
        int k = kg + 16*kk;
        int cp = 2*(k & 31) + (k >> 5);
        float bk = bias[k];
        float win[18];
        #pragma unroll
        for (int m = 0; m < 18; m++) win[m] = Gs[(L0 + m)*66 + cp];
        #pragma unroll
        for (int i = 0; i < 8; i++) {
            float u = 0.f;
            #pragma unroll
            for (int j = 0; j < 11; j++) u = fmaf(wreg[j], win[i + j], u);
            tmax[i] = fmaxf(tmax[i], fmaxf(u + bk, 0.f));
        }
    }
    #pragma unroll
    for (int i = 0; i < 8; i++) {
        float t = tmax[i];
        t = fmaxf(t, __shfl_xor_sync(0xffffffffu, t, 1));
        t = fmaxf(t, __shfl_xor_sync(0xffffffffu, t, 2));
        t = fmaxf(t, __shfl_xor_sync(0xffffffffu, t, 4));
        t = fmaxf(t, __shfl_xor_sync(0xffffffffu, t, 8));
        if (kg == 0) g_t[(size_t)b*LL + l0 + L0 + i] = t;
    }
}

// ============================================================
// K3: single-pass softmax over L (folds 1/L)
// ============================================================
__global__ __launch_bounds__(512) void k_softmax() {
    int b = blockIdx.x;
    int tid = threadIdx.x;
    int wid = tid >> 5, lid = tid & 31;
    __shared__ float red[16], red2[16];

    float4 v = ((const float4*)(g_t + (size_t)b*LL))[tid];

    float mx = fmaxf(fmaxf(v.x, v.y), fmaxf(v.z, v.w));
    for (int o = 16; o; o >>= 1) mx = fmaxf(mx, __shfl_xor_sync(0xffffffffu, mx, o));
    if (lid == 0) red[wid] = mx;
    __syncthreads();
    if (wid == 0) {
        float m = red[lid & 15];
        for (int o = 8; o; o >>= 1) m = fmaxf(m, __shfl_xor_sync(0xffffffffu, m, o));
        if (lid == 0) red[0] = m;
    }
    __syncthreads();
    float m = red[0];

    float e0 = expf(v.x - m), e1 = expf(v.y - m), e2 = expf(v.z - m), e3 = expf(v.w - m);
    float s = e0 + e1 + e2 + e3;
    for (int o = 16; o; o >>= 1) s += __shfl_xor_sync(0xffffffffu, s, o);
    if (lid == 0) red2[wid] = s;
    __syncthreads();
    if (wid == 0) {
        float t = red2[lid & 15];
        for (int o = 8; o; o >>= 1) t += __shfl_xor_sync(0xffffffffu, t, o);
        if (lid == 0) red2[0] = t;
    }
    __syncthreads();
    float scale = 1.f / (red2[0] * (float)LL);

    ((float4*)(g_beta + (size_t)b*LL))[tid] =
        make_float4(e0*scale, e1*scale, e2*scale, e3*scale);
}

// ============================================================
// K4: out[b,k] += sum_l beta[b,l] * VWh[x[b,l], k]
// ============================================================
__global__ __launch_bounds__(128) void k_poolvw(const int* __restrict__ x,
                                                float* __restrict__ out) {
    __shared__ float4 red[128];
    int blk = blockIdx.x;
    int b = blk >> 4, c = blk & 15;
    int t = threadIdx.x;
    int i = t >> 4;
    int q = t & 15;
    int lbase = b*LL + c*128;

    float4 acc = make_float4(0.f, 0.f, 0.f, 0.f);
    #pragma unroll 4
    for (int it = 0; it < 16; it++) {
        int l = it*8 + i;
        float wgt = g_beta[lbase + l];
        int row = __ldg(&x[lbase + l]);
        uint2 hv = *(const uint2*)&g_VWh[(size_t)row*KK + q*4];
        float2 lo = __half22float2(*(__half2*)&hv.x);
        float2 hi = __half22float2(*(__half2*)&hv.y);
        acc.x = fmaf(wgt, lo.x, acc.x);
        acc.y = fmaf(wgt, lo.y, acc.y);
        acc.z = fmaf(wgt, hi.x, acc.z);
        acc.w = fmaf(wgt, hi.y, acc.w);
    }
    red[t] = acc;
    __syncthreads();
    if (t < 64) {
        float4 o = red[t + 64];
        acc = red[t];
        acc.x += o.x; acc.y += o.y; acc.z += o.z; acc.w += o.w;
        red[t] = acc;
    }
    __syncthreads();
    if (t < 32) {
        float4 o = red[t + 32];
        acc = red[t];
        acc.x += o.x; acc.y += o.y; acc.z += o.z; acc.w += o.w;
        red[t] = acc;
    }
    __syncthreads();
    if (t < 16) {
        float4 o = red[t + 16];
        acc = red[t];
        acc.x += o.x; acc.y += o.y; acc.z += o.z; acc.w += o.w;
        atomicAdd(&out[b*KK + t*4 + 0], acc.x);
        atomicAdd(&out[b*KK + t*4 + 1], acc.y);
        atomicAdd(&out[b*KK + t*4 + 2], acc.z);
        atomicAdd(&out[b*KK + t*4 + 3], acc.w);
    }
}

// ============================================================
extern "C" void kernel_launch(void* const* d_in, const int* in_sizes, int n_in,
                              void* d_out, int out_size) {
    const int*   x   = (const int*)d_in[0];
    const float* V   = (const float*)d_in[1];
    const float* C   = (const float*)d_in[2];
    const float* f1w = (const float*)d_in[3];
    const float* f1b = (const float*)d_in[4];
    const float* f2w = (const float*)d_in[5];
    const float* f2b = (const float*)d_in[6];
    float* out = (float*)d_out;

    cudaFuncSetAttribute(k_vocab, cudaFuncAttributeMaxDynamicSharedMemorySize, SMV_TOT);

    k_setup<<<KK, 256>>>(C, f2w);                        // 1
    k_flag<<<NT/512, 512>>>(x, f2b, out);                // 2
    k_compact<<<(VOCAB + 255)/256, 256>>>();             // 3
    k_vocab<<<((VOCAB + 127)/128)*2, 256, SMV_TOT>>>(V); // 4 <- ncu slot
    k_conv<<<dim3(LL/128, BB), 256>>>(x, f1w, f1b);      // 5
    k_softmax<<<BB, 512>>>();                            // 6
    k_poolvw<<<BB*16, 128>>>(x, out);                    // 7
}